// round 14
// baseline (speedup 1.0000x reference)
#include <cuda_runtime.h>
#include <cuda_fp16.h>
#include <cstdint>
#include <math.h>

#define Bb 256
#define Tt 60
#define Cc 512
#define Ee 10
#define Kk 5
#define Hh 8
#define DH 64

// ---------------- scratch (device globals) ----------------
__device__ float g_q[Bb * Cc];
__device__ float g_rk[Bb * Hh * Cc];
__device__ float g_ctx[Bb * Cc];
__device__ float g_tmp[Bb * Cc];
__device__ float g_scr[Bb * Hh * 64];
__device__ int   g_topk_i[Bb * Kk];
__device__ float g_topk_p[Bb * Kk];
__device__ float g_tw[Bb * Kk * Tt];
__device__ float g_sw[Bb * Kk];
__device__ float g_pooled[Bb * Kk * 256];
__device__ float g_pd[Bb * Hh * Cc];
__device__ float g_perexp[Bb * Kk * Cc];
__device__ int   g_glist[Ee * 256];
__device__ int   g_cnt[Ee];
__device__ __half g_dh[Bb * Tt * Cc];
__device__ __half g_w1h[Ee * 256 * Cc];

// ---------------- helpers ----------------
__device__ __forceinline__ float softplus_f(float x) {
    return fmaxf(x, 0.0f) + log1pf(expf(-fabsf(x)));
}
__device__ __forceinline__ uint32_t smem_u32(const void* p) {
    return (uint32_t)__cvta_generic_to_shared(p);
}
__device__ __forceinline__ void ldm_x4(uint32_t* r, uint32_t addr) {
    asm volatile("ldmatrix.sync.aligned.m8n8.x4.shared.b16 {%0,%1,%2,%3}, [%4];"
                 : "=r"(r[0]), "=r"(r[1]), "=r"(r[2]), "=r"(r[3]) : "r"(addr));
}
__device__ __forceinline__ void mma16816(float* c, const uint32_t* a, const uint32_t* b) {
    asm volatile(
        "mma.sync.aligned.m16n8k16.row.col.f32.f16.f16.f32 "
        "{%0,%1,%2,%3}, {%4,%5,%6,%7}, {%8,%9}, {%0,%1,%2,%3};"
        : "+f"(c[0]), "+f"(c[1]), "+f"(c[2]), "+f"(c[3])
        : "r"(a[0]), "r"(a[1]), "r"(a[2]), "r"(a[3]), "r"(b[0]), "r"(b[1]));
}
__device__ __forceinline__ void cp16(uint32_t dst, const void* src, int srcsize) {
    asm volatile("cp.async.cg.shared.global [%0], [%1], 16, %2;\n"
                 :: "r"(dst), "l"(src), "r"(srcsize));
}
__device__ __forceinline__ void cp_commit() {
    asm volatile("cp.async.commit_group;\n");
}
template <int N>
__device__ __forceinline__ void cp_wait() {
    asm volatile("cp.async.wait_group %0;\n" :: "n"(N));
}

// ---------------- prep: fp16 conversions (x4 vectorized) + g_cnt zeroing ----------------
__global__ void prep_kernel(const float* __restrict__ data, const float* __restrict__ w1) {
    int i = (blockIdx.x * 256 + threadIdx.x) * 4;
    if (i < Bb * Tt * Cc) {
        float4 v = *(const float4*)(data + i);
        *(__half2*)(g_dh + i) = __floats2half2_rn(v.x, v.y);
        *(__half2*)(g_dh + i + 2) = __floats2half2_rn(v.z, v.w);
    }
    if (i < Ee * 256 * Cc) {
        float4 v = *(const float4*)(w1 + i);
        *(__half2*)(g_w1h + i) = __floats2half2_rn(v.x, v.y);
        *(__half2*)(g_w1h + i + 2) = __floats2half2_rn(v.z, v.w);
    }
    int t = blockIdx.x * 256 + threadIdx.x;
    if (t < Ee) g_cnt[t] = 0;
}

// ---------------- generic 32x64 SGEMM, double-buffered, k-step 32 ----------------
__device__ __forceinline__ void sgemm_body32(const float* __restrict__ A, int lda,
                                             const float* __restrict__ W,
                                             const float* __restrict__ bias,
                                             float* __restrict__ C, int ldc,
                                             float alpha, int n0, int m0) {
    __shared__ float As[2][32 * 36];
    __shared__ float Ws[2][32 * 68];
    int tid = threadIdx.x;
    int ty = tid >> 4, tx = tid & 15;
    float acc[2][4] = {};
    float ar[4], wr[8];
#pragma unroll
    for (int r = 0; r < 4; r++) { int l = r * 256 + tid; int m = l >> 5, kc = l & 31; ar[r] = A[(m0 + m) * lda + kc]; }
#pragma unroll
    for (int r = 0; r < 8; r++) { int l = r * 256 + tid; int n = l >> 5, kc = l & 31; wr[r] = W[(n0 + n) * 512 + kc]; }
#pragma unroll
    for (int r = 0; r < 4; r++) { int l = r * 256 + tid; int m = l >> 5, kc = l & 31; As[0][kc * 36 + m] = ar[r]; }
#pragma unroll
    for (int r = 0; r < 8; r++) { int l = r * 256 + tid; int n = l >> 5, kc = l & 31; Ws[0][kc * 68 + n] = wr[r]; }
    for (int i = 0; i < 16; i++) {
        int cur = i & 1;
        if (i < 15) {
            int k0 = (i + 1) * 32;
#pragma unroll
            for (int r = 0; r < 4; r++) { int l = r * 256 + tid; int m = l >> 5, kc = l & 31; ar[r] = A[(m0 + m) * lda + k0 + kc]; }
#pragma unroll
            for (int r = 0; r < 8; r++) { int l = r * 256 + tid; int n = l >> 5, kc = l & 31; wr[r] = W[(n0 + n) * 512 + k0 + kc]; }
        }
        __syncthreads();
#pragma unroll
        for (int kc = 0; kc < 32; kc++) {
            float a0 = As[cur][kc * 36 + ty * 2];
            float a1 = As[cur][kc * 36 + ty * 2 + 1];
            float4 bv = *(const float4*)&Ws[cur][kc * 68 + tx * 4];
            acc[0][0] += a0 * bv.x; acc[0][1] += a0 * bv.y;
            acc[0][2] += a0 * bv.z; acc[0][3] += a0 * bv.w;
            acc[1][0] += a1 * bv.x; acc[1][1] += a1 * bv.y;
            acc[1][2] += a1 * bv.z; acc[1][3] += a1 * bv.w;
        }
        if (i < 15) {
            int nb = cur ^ 1;
#pragma unroll
            for (int r = 0; r < 4; r++) { int l = r * 256 + tid; int m = l >> 5, kc = l & 31; As[nb][kc * 36 + m] = ar[r]; }
#pragma unroll
            for (int r = 0; r < 8; r++) { int l = r * 256 + tid; int n = l >> 5, kc = l & 31; Ws[nb][kc * 68 + n] = wr[r]; }
        }
    }
#pragma unroll
    for (int i = 0; i < 2; i++) {
        int m = m0 + ty * 2 + i;
#pragma unroll
        for (int j = 0; j < 4; j++) {
            int n = n0 + tx * 4 + j;
            C[m * ldc + n] = alpha * (acc[i][j] + bias[n]);
        }
    }
}
__global__ void proj_q_kernel(const float* __restrict__ qst,
                              const float* __restrict__ ipw,
                              const float* __restrict__ ipb) {
    sgemm_body32(qst, 512, ipw, ipb, g_q, 512, 0.125f, blockIdx.x * 64, blockIdx.y * 32);
}
__global__ void proj_tmp_kernel(const float* __restrict__ opw,
                                const float* __restrict__ opb) {
    sgemm_body32(g_ctx, 512, opw, opb, g_tmp, 512, 1.0f, blockIdx.x * 64, blockIdx.y * 32);
}
__global__ void ctx_kernel(const float* __restrict__ ipw,
                           const float* __restrict__ ipb) {
    int h = blockIdx.x;
    sgemm_body32(g_pd + h * 512, Hh * 512,
                 ipw + (1024 + h * 64) * 512,
                 ipb + 1024 + h * 64,
                 g_ctx + h * 64, 512, 1.0f, 0, blockIdx.y * 32);
}

// ---------------- rk = q_h @ Wk_h : 32x64 tiles, grid (8n, 8m, 8h) ----------------
__global__ void rk_kernel(const float* __restrict__ ipw) {
    __shared__ float As[16 * 36];
    __shared__ float Ws[16 * 68];
    int n0 = blockIdx.x * 64, m0 = blockIdx.y * 32, h = blockIdx.z;
    int tid = threadIdx.x, ty = tid >> 4, tx = tid & 15;
    float acc[2][4] = {};
    for (int kk = 0; kk < 64; kk += 16) {
#pragma unroll
        for (int r = 0; r < 2; r++) {
            int l = r * 256 + tid;
            int m = l >> 4, kc = l & 15;
            As[kc * 36 + m] = g_q[(m0 + m) * 512 + h * 64 + kk + kc];
        }
#pragma unroll
        for (int r = 0; r < 4; r++) {
            int l = r * 256 + tid;
            int kc = l >> 6, n = l & 63;
            Ws[kc * 68 + n] = ipw[(512 + h * 64 + kk + kc) * 512 + n0 + n];
        }
        __syncthreads();
#pragma unroll
        for (int kc = 0; kc < 16; kc++) {
            float a0 = As[kc * 36 + ty * 2];
            float a1 = As[kc * 36 + ty * 2 + 1];
            float4 bv = *(const float4*)&Ws[kc * 68 + tx * 4];
            acc[0][0] += a0 * bv.x; acc[0][1] += a0 * bv.y;
            acc[0][2] += a0 * bv.z; acc[0][3] += a0 * bv.w;
            acc[1][0] += a1 * bv.x; acc[1][1] += a1 * bv.y;
            acc[1][2] += a1 * bv.z; acc[1][3] += a1 * bv.w;
        }
        __syncthreads();
    }
#pragma unroll
    for (int i = 0; i < 2; i++) {
        int b = m0 + ty * 2 + i;
#pragma unroll
        for (int j = 0; j < 4; j++)
            g_rk[(b * Hh + h) * 512 + n0 + tx * 4 + j] = acc[i][j];
    }
}

// ---------------- attention scores: grid (8, B), 128 threads, low reg pressure ----------------
// block (q, b): timesteps q*8 .. q*8+7 (warp w does 2), heads in 2 passes of 4
__global__ void score_kernel(const float* __restrict__ data,
                             const float* __restrict__ ipb) {
    int b = blockIdx.y, q = blockIdx.x;
    int tid = threadIdx.x;
    __shared__ float rks[8 * 512];
    __shared__ float qb_s[8];
    const float* rkg = g_rk + b * (Hh * 512);
    for (int i = tid * 4; i < 4096; i += 512)
        *(float4*)&rks[i] = *(const float4*)&rkg[i];
    int w = tid >> 5, lane = tid & 31;
    // qb: warp w computes heads 2w, 2w+1
#pragma unroll
    for (int hh = 0; hh < 2; hh++) {
        int h = w * 2 + hh;
        float s = g_q[b * 512 + h * 64 + lane] * ipb[512 + h * 64 + lane]
                + g_q[b * 512 + h * 64 + 32 + lane] * ipb[512 + h * 64 + 32 + lane];
#pragma unroll
        for (int o = 16; o > 0; o >>= 1) s += __shfl_down_sync(0xffffffffu, s, o);
        if (lane == 0) qb_s[h] = s;
    }
    __syncthreads();
    for (int ti = 0; ti < 2; ti++) {
        int t = q * 8 + w * 2 + ti;
        if (t < Tt) {
            const float* dp = data + (b * Tt + t) * 512;
            for (int hp = 0; hp < 2; hp++) {
                float part[4] = {};
#pragma unroll
                for (int j = 0; j < 4; j++) {
                    float4 d4 = *(const float4*)&dp[j * 128 + lane * 4];
#pragma unroll
                    for (int h4 = 0; h4 < 4; h4++) {
                        float4 r4 = *(const float4*)&rks[(hp * 4 + h4) * 512 + j * 128 + lane * 4];
                        part[h4] += d4.x * r4.x + d4.y * r4.y + d4.z * r4.z + d4.w * r4.w;
                    }
                }
#pragma unroll
                for (int h4 = 0; h4 < 4; h4++) {
                    float s = part[h4];
#pragma unroll
                    for (int o = 16; o > 0; o >>= 1) s += __shfl_down_sync(0xffffffffu, s, o);
                    if (lane == 0) g_scr[(b * Hh + hp * 4 + h4) * 64 + t] = s + qb_s[hp * 4 + h4];
                }
            }
        }
    }
}

// ---------------- softmax + pooled data: grid (4, B), 128 threads ----------------
__global__ void softmax_pool_kernel(const float* __restrict__ data) {
    int b = blockIdx.y, qc = blockIdx.x;
    int tid = threadIdx.x;
    __shared__ float p_s[8][64];
    int w = tid >> 5, lane = tid & 31;
    // softmax: warp w handles heads 2w, 2w+1 (redundant across 4 blocks; identical fp32 ops)
#pragma unroll
    for (int hh = 0; hh < 2; hh++) {
        int h = w * 2 + hh;
        float v0 = (lane < Tt) ? g_scr[(b * Hh + h) * 64 + lane] : -1e30f;
        float v1 = (lane + 32 < Tt) ? g_scr[(b * Hh + h) * 64 + lane + 32] : -1e30f;
        float m = fmaxf(v0, v1);
#pragma unroll
        for (int o = 16; o > 0; o >>= 1) m = fmaxf(m, __shfl_xor_sync(0xffffffffu, m, o));
        float e0 = (lane < Tt) ? expf(v0 - m) : 0.0f;
        float e1 = (lane + 32 < Tt) ? expf(v1 - m) : 0.0f;
        float s = e0 + e1;
#pragma unroll
        for (int o = 16; o > 0; o >>= 1) s += __shfl_xor_sync(0xffffffffu, s, o);
        float inv = 1.0f / s;
        p_s[h][lane] = e0 * inv;
        p_s[h][lane + 32] = e1 * inv;
    }
    __syncthreads();
    int c = qc * 128 + tid;
    float acc[8] = {};
    const float* dpb = data + b * Tt * 512 + c;
#pragma unroll 4
    for (int t = 0; t < Tt; t++) {
        float d = dpb[t * 512];
#pragma unroll
        for (int h = 0; h < 8; h++) acc[h] += p_s[h][t] * d;
    }
#pragma unroll
    for (int h = 0; h < 8; h++)
        g_pd[(b * Hh + h) * 512 + c] = acc[h];
}

// ---------------- router + top-k + beta weights + inlined group build ----------------
__global__ void router_kernel(const float* __restrict__ router_w,
                              const float* __restrict__ router_b,
                              const float* __restrict__ beta_w,
                              const float* __restrict__ beta_b) {
    int b = blockIdx.x;
    __shared__ float tmp_s[512];
    __shared__ float logit[32];
    __shared__ float al[Ee], be[Ee];
    __shared__ int sel_i[Kk];
    __shared__ float w_s[Kk * Tt];
    int tid = threadIdx.x;
    for (int c = tid; c < 512; c += 256) tmp_s[c] = g_tmp[b * Cc + c];
    __syncthreads();
    int w = tid >> 5, lane = tid & 31;
    for (int r = w; r < 30; r += 8) {
        const float* wr; float bias;
        if (r < Ee) { wr = router_w + r * 512; bias = router_b[r]; }
        else { wr = beta_w + (r - Ee) * 512; bias = beta_b[r - Ee]; }
        float s = 0.f;
        for (int c = lane; c < 512; c += 32) s += wr[c] * tmp_s[c];
#pragma unroll
        for (int o = 16; o > 0; o >>= 1) s += __shfl_down_sync(0xffffffffu, s, o);
        if (lane == 0) logit[r] = s + bias;
    }
    __syncthreads();
    if (tid < Ee) {
        al[tid] = softplus_f(logit[Ee + 2 * tid]) + 1e-6f;
        be[tid] = softplus_f(logit[Ee + 2 * tid + 1]) + 1e-6f;
    }
    if (tid == 0) {
        float m = logit[0];
        for (int e = 1; e < Ee; e++) m = fmaxf(m, logit[e]);
        float pe[Ee]; float s = 0.f;
        for (int e = 0; e < Ee; e++) { pe[e] = expf(logit[e] - m); s += pe[e]; }
        float invs = 1.0f / s;
        for (int e = 0; e < Ee; e++) pe[e] *= invs;
        bool used[Ee] = {};
        float psum = 0.f; float sp[Kk];
        for (int kk = 0; kk < Kk; kk++) {
            int best = 0; float bv = -1.f;
            for (int e = 0; e < Ee; e++)
                if (!used[e] && pe[e] > bv) { bv = pe[e]; best = e; }
            used[best] = true; sel_i[kk] = best; sp[kk] = bv; psum += bv;
        }
        float inv = 1.0f / (psum + 1e-8f);
        for (int kk = 0; kk < Kk; kk++) {
            int e = sel_i[kk];
            g_topk_i[b * Kk + kk] = e;
            g_topk_p[b * Kk + kk] = sp[kk] * inv;
            int slot = atomicAdd(&g_cnt[e], 1);
            g_glist[e * 256 + slot] = b * Kk + kk;
        }
    }
    __syncthreads();
    for (int i = tid; i < Kk * Tt; i += 256) {
        int kk = i / Tt, t = i % Tt;
        int e = sel_i[kk];
        float a = al[e], bb = be[e];
        float tt = (float)t / 59.0f;
        float lt = logf(tt + 1e-12f);
        float l1 = logf(1.0f - tt + 1e-12f);
        float norm = lgammaf(a) + lgammaf(bb) - lgammaf(a + bb);
        w_s[i] = expf((a - 1.0f) * lt + (bb - 1.0f) * l1 - norm);
    }
    __syncthreads();
    if (tid < Kk) {
        float m = 0.f;
        for (int t = 0; t < Tt; t++) m = fmaxf(m, w_s[tid * Tt + t]);
        float inv = 1.0f / (m + 1e-8f);
        float s = 0.f;
        for (int t = 0; t < Tt; t++) {
            float v = w_s[tid * Tt + t] * inv;
            g_tw[(b * Kk + tid) * Tt + t] = v;
            s += v;
        }
        g_sw[b * Kk + tid] = s;
    }
}

// ---------------- layer1: fp16 tensor cores, M=64 N=128 tiles, cp.async double-buffered ----------------
#define L1_SMEM 57664
__global__ void layer1_mma_kernel(const float* __restrict__ b1) {
    extern __shared__ char sm[];
    __half* As = (__half*)sm;
    __half* Bs = (__half*)(sm + 18432);
    float* tw_s = (float*)(sm + 55296);
    float* red = (float*)(sm + 55552);
    int bk = blockIdx.y;
    int b = bk / Kk;
    int n0blk = blockIdx.x * 128;
    int e = g_topk_i[bk];
    int tid = threadIdx.x;
    int warp = tid >> 5, lane = tid & 31;
    int mw = warp >> 1, nw = warp & 1;

    if (tid < 64) tw_s[tid] = (tid < Tt) ? g_tw[bk * Tt + tid] : 0.0f;

    const __half* Ap = g_dh + (long)b * (Tt * Cc);
    const __half* Wp = g_w1h + (long)e * (256 * Cc) + (long)n0blk * Cc;

    auto issue = [&](int ch, int buf) {
        int kb = ch * 64;
#pragma unroll
        for (int it = 0; it < 2; it++) {
            int idx = it * 256 + tid;
            int row = idx >> 3, ub = (idx & 7) * 8;
            const __half* a = (row < Tt) ? (Ap + row * Cc + kb + ub) : Ap;
            cp16(smem_u32(As + buf * 4608 + row * 72 + ub), a, row < Tt ? 16 : 0);
        }
#pragma unroll
        for (int it = 0; it < 4; it++) {
            int idx = it * 256 + tid;
            int row = idx >> 3, ub = (idx & 7) * 8;
            cp16(smem_u32(Bs + buf * 9216 + row * 72 + ub), Wp + row * Cc + kb + ub, 16);
        }
        cp_commit();
    };

    float acc[8][4] = {};
    issue(0, 0);
    for (int ch = 0; ch < 8; ch++) {
        int cur = ch & 1;
        if (ch < 7) { issue(ch + 1, cur ^ 1); cp_wait<1>(); }
        else { cp_wait<0>(); }
        __syncthreads();
#pragma unroll
        for (int ks = 0; ks < 4; ks++) {
            uint32_t a[4];
            int arow = mw * 16 + (lane & 15);
            int acol = ks * 16 + (lane >> 4) * 8;
            ldm_x4(a, smem_u32(As + cur * 4608 + arow * 72 + acol));
            uint32_t bf[16];
#pragma unroll
            for (int half = 0; half < 4; half++) {
                int nbase = nw * 64 + half * 16;
                int grp = lane >> 3, l8 = lane & 7;
                int nrow = nbase + (grp >> 1) * 8 + l8;
                int kcol = ks * 16 + (grp & 1) * 8;
                ldm_x4(bf + half * 4, smem_u32(Bs + cur * 9216 + nrow * 72 + kcol));
            }
#pragma unroll
            for (int j = 0; j < 8; j++) mma16816(acc[j], a, bf + j * 2);
        }
        __syncthreads();
    }
    int g = lane >> 2, t4 = lane & 3;
    int r0 = mw * 16 + g, r1 = r0 + 8;
    float w0 = tw_s[r0], w1 = tw_s[r1];
#pragma unroll
    for (int j = 0; j < 8; j++) {
        int nc0 = nw * 64 + j * 8 + t4 * 2;
        float bias0 = b1[e * 256 + n0blk + nc0];
        float bias1 = b1[e * 256 + n0blk + nc0 + 1];
        float s0 = w0 * fmaxf(acc[j][0] + bias0, 0.f) + w1 * fmaxf(acc[j][2] + bias0, 0.f);
        float s1 = w0 * fmaxf(acc[j][1] + bias1, 0.f) + w1 * fmaxf(acc[j][3] + bias1, 0.f);
#pragma unroll
        for (int o = 16; o >= 4; o >>= 1) {
            s0 += __shfl_down_sync(0xffffffffu, s0, o);
            s1 += __shfl_down_sync(0xffffffffu, s1, o);
        }
        if (g == 0) {
            red[mw * 132 + nc0] = s0;
            red[mw * 132 + nc0 + 1] = s1;
        }
    }
    __syncthreads();
    if (tid < 128) {
        float p = red[tid] + red[132 + tid] + red[264 + tid] + red[396 + tid];
        g_pooled[bk * 256 + n0blk + tid] = p;
    }
}

// ---------------- layer2: expert-grouped GEMM ----------------
__global__ void layer2_kernel(const float* __restrict__ w2,
                              const float* __restrict__ b2) {
    int nt = blockIdx.x, mt = blockIdx.y, e = blockIdx.z;
    int cnt = g_cnt[e];
    if (mt * 32 >= cnt) return;
    __shared__ float P[32 * 260];
    __shared__ float Ws[64 * 65];
    __shared__ int prs[32];
    int tid = threadIdx.x;
    int rows = cnt - mt * 32; if (rows > 32) rows = 32;
    if (tid < 32) prs[tid] = (tid < rows) ? g_glist[e * 256 + mt * 32 + tid] : -1;
    __syncthreads();
#pragma unroll
    for (int r = 0; r < 8; r++) {
        int fi = r * 256 + tid;
        int row = fi >> 6, c4 = (fi & 63) * 4;
        float4 v = make_float4(0.f, 0.f, 0.f, 0.f);
        int p = prs[row];
        if (p >= 0) v = *(const float4*)&g_pooled[p * 256 + c4];
        *(float4*)&P[row * 260 + c4] = v;
    }
    int nn = tid & 31, mg = tid >> 5;
    float acc[4][2] = {};
    for (int q = 0; q < 4; q++) {
        __syncthreads();
#pragma unroll
        for (int r = 0; r < 16; r++) {
            int fi = r * 256 + tid;
            int n = fi >> 6, kc = fi & 63;
            Ws[n * 65 + kc] = w2[(e * 512 + nt * 64 + n) * 256 + q * 64 + kc];
        }
        __syncthreads();
#pragma unroll 4
        for (int kc = 0; kc < 64; kc++) {
            float w0 = Ws[nn * 65 + kc];
            float w1 = Ws[(nn + 32) * 65 + kc];
#pragma unroll
            for (int mi = 0; mi < 4; mi++) {
                float pv = P[(mg + mi * 8) * 260 + q * 64 + kc];
                acc[mi][0] += pv * w0;
                acc[mi][1] += pv * w1;
            }
        }
    }
#pragma unroll
    for (int mi = 0; mi < 4; mi++) {
        int row = mg + mi * 8;
        int p = prs[row];
        if (p >= 0) {
            float sw = g_sw[p];
            int cc0 = nt * 64 + nn, cc1 = cc0 + 32;
            g_perexp[p * 512 + cc0] = acc[mi][0] + sw * b2[e * 512 + cc0];
            g_perexp[p * 512 + cc1] = acc[mi][1] + sw * b2[e * 512 + cc1];
        }
    }
}

// ---------------- combine + LayerNorm ----------------
__global__ void ln_kernel(const float* __restrict__ ln_g,
                          const float* __restrict__ ln_b,
                          float* __restrict__ out) {
    int b = blockIdx.x, tid = threadIdx.x;
    __shared__ float red[18];
    float y0 = 0.f, y1 = 0.f;
#pragma unroll
    for (int kk = 0; kk < Kk; kk++) {
        float p = g_topk_p[b * Kk + kk];
        const float* pe = g_perexp + (b * Kk + kk) * 512;
        y0 += p * pe[tid];
        y1 += p * pe[tid + 256];
    }
    float s = y0 + y1, sq = y0 * y0 + y1 * y1;
    int w = tid >> 5, lane = tid & 31;
#pragma unroll
    for (int o = 16; o > 0; o >>= 1) {
        s += __shfl_down_sync(0xffffffffu, s, o);
        sq += __shfl_down_sync(0xffffffffu, sq, o);
    }
    if (lane == 0) { red[w] = s; red[8 + w] = sq; }
    __syncthreads();
    if (tid == 0) {
        float S = 0.f, SQ = 0.f;
        for (int i = 0; i < 8; i++) { S += red[i]; SQ += red[8 + i]; }
        red[16] = S; red[17] = SQ;
    }
    __syncthreads();
    float mean = red[16] * (1.0f / 512.0f);
    float var = red[17] * (1.0f / 512.0f) - mean * mean;
    float rstd = rsqrtf(var + 1e-5f);
    out[b * Cc + tid] = (y0 - mean) * rstd * ln_g[tid] + ln_b[tid];
    out[b * Cc + tid + 256] = (y1 - mean) * rstd * ln_g[tid + 256] + ln_b[tid + 256];
}

// ---------------- launch ----------------
extern "C" void kernel_launch(void* const* d_in, const int* in_sizes, int n_in,
                              void* d_out, int out_size) {
    const float* qst = (const float*)d_in[0];
    const float* data = (const float*)d_in[1];
    const float* ipw = (const float*)d_in[2];
    const float* ipb = (const float*)d_in[3];
    const float* opw = (const float*)d_in[4];
    const float* opb = (const float*)d_in[5];
    const float* rw  = (const float*)d_in[6];
    const float* rb  = (const float*)d_in[7];
    const float* bw  = (const float*)d_in[8];
    const float* bb  = (const float*)d_in[9];
    const float* w1  = (const float*)d_in[10];
    const float* b1  = (const float*)d_in[11];
    const float* w2  = (const float*)d_in[12];
    const float* b2  = (const float*)d_in[13];
    const float* lng = (const float*)d_in[14];
    const float* lnb = (const float*)d_in[15];
    float* out = (float*)d_out;

    static bool init_done = false;
    static cudaStream_t s2;
    static cudaEvent_t ev_fork, ev_join;
    if (!init_done) {
        cudaFuncSetAttribute(layer1_mma_kernel,
                             cudaFuncAttributeMaxDynamicSharedMemorySize, L1_SMEM);
        cudaStreamCreateWithFlags(&s2, cudaStreamNonBlocking);
        cudaEventCreateWithFlags(&ev_fork, cudaEventDisableTiming);
        cudaEventCreateWithFlags(&ev_join, cudaEventDisableTiming);
        init_done = true;
    }

    // fork: prep runs concurrently with the q->rk->score chain
    cudaEventRecord(ev_fork, 0);
    cudaStreamWaitEvent(s2, ev_fork, 0);
    prep_kernel<<<(Bb * Tt * Cc / 4 + 255) / 256, 256, 0, s2>>>(data, w1);
    cudaEventRecord(ev_join, s2);

    proj_q_kernel<<<dim3(8, 8), 256>>>(qst, ipw, ipb);
    rk_kernel<<<dim3(8, 8, 8), 256>>>(ipw);
    score_kernel<<<dim3(8, Bb), 128>>>(data, ipb);
    softmax_pool_kernel<<<dim3(4, Bb), 128>>>(data);
    ctx_kernel<<<dim3(8, 8), 256>>>(ipw, ipb);
    proj_tmp_kernel<<<dim3(8, 8), 256>>>(opw, opb);
    // join before router (router's atomicAdd needs g_cnt zeroed by prep)
    cudaStreamWaitEvent(0, ev_join, 0);
    router_kernel<<<Bb, 256>>>(rw, rb, bw, bb);
    layer1_mma_kernel<<<dim3(2, Bb * Kk), 256, L1_SMEM>>>(b1);
    layer2_kernel<<<dim3(8, 8, Ee), 256>>>(w2, b2);
    ln_kernel<<<Bb, 256>>>(lng, lnb, out);
}

// round 15
// speedup vs baseline: 1.1942x; 1.1942x over previous
#include <cuda_runtime.h>
#include <cuda_fp16.h>
#include <cstdint>
#include <math.h>

#define Bb 256
#define Tt 60
#define Cc 512
#define Ee 10
#define Kk 5
#define Hh 8
#define DH 64

// ---------------- scratch (device globals) ----------------
__device__ float g_q[Bb * Cc];
__device__ float g_rk[Bb * Hh * Cc];
__device__ float g_ctx[Bb * Cc];
__device__ float g_tmp[Bb * Cc];
__device__ float g_scr[Bb * Hh * 64];
__device__ int   g_topk_i[Bb * Kk];
__device__ float g_topk_p[Bb * Kk];
__device__ float g_tw[Bb * Kk * Tt];
__device__ float g_sw[Bb * Kk];
__device__ float g_pooled[Bb * Kk * 256];
__device__ float g_pd[Bb * Hh * Cc];
__device__ float g_perexp[Bb * Kk * Cc];
__device__ int   g_glist[Ee * 256];
__device__ int   g_cnt[Ee];
__device__ __half g_dh[Bb * Tt * Cc];
__device__ __half g_w1h[Ee * 256 * Cc];

// ---------------- helpers ----------------
__device__ __forceinline__ float softplus_f(float x) {
    return fmaxf(x, 0.0f) + log1pf(expf(-fabsf(x)));
}
__device__ __forceinline__ uint32_t smem_u32(const void* p) {
    return (uint32_t)__cvta_generic_to_shared(p);
}
__device__ __forceinline__ void ldm_x4(uint32_t* r, uint32_t addr) {
    asm volatile("ldmatrix.sync.aligned.m8n8.x4.shared.b16 {%0,%1,%2,%3}, [%4];"
                 : "=r"(r[0]), "=r"(r[1]), "=r"(r[2]), "=r"(r[3]) : "r"(addr));
}
__device__ __forceinline__ void mma16816(float* c, const uint32_t* a, const uint32_t* b) {
    asm volatile(
        "mma.sync.aligned.m16n8k16.row.col.f32.f16.f16.f32 "
        "{%0,%1,%2,%3}, {%4,%5,%6,%7}, {%8,%9}, {%0,%1,%2,%3};"
        : "+f"(c[0]), "+f"(c[1]), "+f"(c[2]), "+f"(c[3])
        : "r"(a[0]), "r"(a[1]), "r"(a[2]), "r"(a[3]), "r"(b[0]), "r"(b[1]));
}
__device__ __forceinline__ void cp16(uint32_t dst, const void* src, int srcsize) {
    asm volatile("cp.async.cg.shared.global [%0], [%1], 16, %2;\n"
                 :: "r"(dst), "l"(src), "r"(srcsize));
}
__device__ __forceinline__ void cp_commit() {
    asm volatile("cp.async.commit_group;\n");
}
template <int N>
__device__ __forceinline__ void cp_wait() {
    asm volatile("cp.async.wait_group %0;\n" :: "n"(N));
}

// ---------------- prep: fp16 conversions (x4 vectorized) + g_cnt zeroing ----------------
__global__ void prep_kernel(const float* __restrict__ data, const float* __restrict__ w1) {
    int i = (blockIdx.x * 256 + threadIdx.x) * 4;
    if (i < Bb * Tt * Cc) {
        float4 v = *(const float4*)(data + i);
        *(__half2*)(g_dh + i) = __floats2half2_rn(v.x, v.y);
        *(__half2*)(g_dh + i + 2) = __floats2half2_rn(v.z, v.w);
    }
    if (i < Ee * 256 * Cc) {
        float4 v = *(const float4*)(w1 + i);
        *(__half2*)(g_w1h + i) = __floats2half2_rn(v.x, v.y);
        *(__half2*)(g_w1h + i + 2) = __floats2half2_rn(v.z, v.w);
    }
    int t = blockIdx.x * 256 + threadIdx.x;
    if (t < Ee) g_cnt[t] = 0;
}

// ---------------- generic 32x64 SGEMM, double-buffered, k-step 32 ----------------
__device__ __forceinline__ void sgemm_body32(const float* __restrict__ A, int lda,
                                             const float* __restrict__ W,
                                             const float* __restrict__ bias,
                                             float* __restrict__ C, int ldc,
                                             float alpha, int n0, int m0) {
    __shared__ float As[2][32 * 36];
    __shared__ float Ws[2][32 * 68];
    int tid = threadIdx.x;
    int ty = tid >> 4, tx = tid & 15;
    float acc[2][4] = {};
    float ar[4], wr[8];
#pragma unroll
    for (int r = 0; r < 4; r++) { int l = r * 256 + tid; int m = l >> 5, kc = l & 31; ar[r] = A[(m0 + m) * lda + kc]; }
#pragma unroll
    for (int r = 0; r < 8; r++) { int l = r * 256 + tid; int n = l >> 5, kc = l & 31; wr[r] = W[(n0 + n) * 512 + kc]; }
#pragma unroll
    for (int r = 0; r < 4; r++) { int l = r * 256 + tid; int m = l >> 5, kc = l & 31; As[0][kc * 36 + m] = ar[r]; }
#pragma unroll
    for (int r = 0; r < 8; r++) { int l = r * 256 + tid; int n = l >> 5, kc = l & 31; Ws[0][kc * 68 + n] = wr[r]; }
    for (int i = 0; i < 16; i++) {
        int cur = i & 1;
        if (i < 15) {
            int k0 = (i + 1) * 32;
#pragma unroll
            for (int r = 0; r < 4; r++) { int l = r * 256 + tid; int m = l >> 5, kc = l & 31; ar[r] = A[(m0 + m) * lda + k0 + kc]; }
#pragma unroll
            for (int r = 0; r < 8; r++) { int l = r * 256 + tid; int n = l >> 5, kc = l & 31; wr[r] = W[(n0 + n) * 512 + k0 + kc]; }
        }
        __syncthreads();
#pragma unroll
        for (int kc = 0; kc < 32; kc++) {
            float a0 = As[cur][kc * 36 + ty * 2];
            float a1 = As[cur][kc * 36 + ty * 2 + 1];
            float4 bv = *(const float4*)&Ws[cur][kc * 68 + tx * 4];
            acc[0][0] += a0 * bv.x; acc[0][1] += a0 * bv.y;
            acc[0][2] += a0 * bv.z; acc[0][3] += a0 * bv.w;
            acc[1][0] += a1 * bv.x; acc[1][1] += a1 * bv.y;
            acc[1][2] += a1 * bv.z; acc[1][3] += a1 * bv.w;
        }
        if (i < 15) {
            int nb = cur ^ 1;
#pragma unroll
            for (int r = 0; r < 4; r++) { int l = r * 256 + tid; int m = l >> 5, kc = l & 31; As[nb][kc * 36 + m] = ar[r]; }
#pragma unroll
            for (int r = 0; r < 8; r++) { int l = r * 256 + tid; int n = l >> 5, kc = l & 31; Ws[nb][kc * 68 + n] = wr[r]; }
        }
    }
#pragma unroll
    for (int i = 0; i < 2; i++) {
        int m = m0 + ty * 2 + i;
#pragma unroll
        for (int j = 0; j < 4; j++) {
            int n = n0 + tx * 4 + j;
            C[m * ldc + n] = alpha * (acc[i][j] + bias[n]);
        }
    }
}
__global__ void proj_q_kernel(const float* __restrict__ qst,
                              const float* __restrict__ ipw,
                              const float* __restrict__ ipb) {
    sgemm_body32(qst, 512, ipw, ipb, g_q, 512, 0.125f, blockIdx.x * 64, blockIdx.y * 32);
}
__global__ void proj_tmp_kernel(const float* __restrict__ opw,
                                const float* __restrict__ opb) {
    sgemm_body32(g_ctx, 512, opw, opb, g_tmp, 512, 1.0f, blockIdx.x * 64, blockIdx.y * 32);
}
__global__ void ctx_kernel(const float* __restrict__ ipw,
                           const float* __restrict__ ipb) {
    int h = blockIdx.x;
    sgemm_body32(g_pd + h * 512, Hh * 512,
                 ipw + (1024 + h * 64) * 512,
                 ipb + 1024 + h * 64,
                 g_ctx + h * 64, 512, 1.0f, 0, blockIdx.y * 32);
}

// ---------------- rk = q_h @ Wk_h : 32x64 tiles, grid (8n, 8m, 8h) ----------------
__global__ void rk_kernel(const float* __restrict__ ipw) {
    __shared__ float As[16 * 36];
    __shared__ float Ws[16 * 68];
    int n0 = blockIdx.x * 64, m0 = blockIdx.y * 32, h = blockIdx.z;
    int tid = threadIdx.x, ty = tid >> 4, tx = tid & 15;
    float acc[2][4] = {};
    for (int kk = 0; kk < 64; kk += 16) {
#pragma unroll
        for (int r = 0; r < 2; r++) {
            int l = r * 256 + tid;
            int m = l >> 4, kc = l & 15;
            As[kc * 36 + m] = g_q[(m0 + m) * 512 + h * 64 + kk + kc];
        }
#pragma unroll
        for (int r = 0; r < 4; r++) {
            int l = r * 256 + tid;
            int kc = l >> 6, n = l & 63;
            Ws[kc * 68 + n] = ipw[(512 + h * 64 + kk + kc) * 512 + n0 + n];
        }
        __syncthreads();
#pragma unroll
        for (int kc = 0; kc < 16; kc++) {
            float a0 = As[kc * 36 + ty * 2];
            float a1 = As[kc * 36 + ty * 2 + 1];
            float4 bv = *(const float4*)&Ws[kc * 68 + tx * 4];
            acc[0][0] += a0 * bv.x; acc[0][1] += a0 * bv.y;
            acc[0][2] += a0 * bv.z; acc[0][3] += a0 * bv.w;
            acc[1][0] += a1 * bv.x; acc[1][1] += a1 * bv.y;
            acc[1][2] += a1 * bv.z; acc[1][3] += a1 * bv.w;
        }
        __syncthreads();
    }
#pragma unroll
    for (int i = 0; i < 2; i++) {
        int b = m0 + ty * 2 + i;
#pragma unroll
        for (int j = 0; j < 4; j++)
            g_rk[(b * Hh + h) * 512 + n0 + tx * 4 + j] = acc[i][j];
    }
}

// ---------------- attention scores: grid (8, B), 128 threads, low reg pressure ----------------
__global__ void score_kernel(const float* __restrict__ data,
                             const float* __restrict__ ipb) {
    int b = blockIdx.y, q = blockIdx.x;
    int tid = threadIdx.x;
    __shared__ float rks[8 * 512];
    __shared__ float qb_s[8];
    const float* rkg = g_rk + b * (Hh * 512);
    for (int i = tid * 4; i < 4096; i += 512)
        *(float4*)&rks[i] = *(const float4*)&rkg[i];
    int w = tid >> 5, lane = tid & 31;
#pragma unroll
    for (int hh = 0; hh < 2; hh++) {
        int h = w * 2 + hh;
        float s = g_q[b * 512 + h * 64 + lane] * ipb[512 + h * 64 + lane]
                + g_q[b * 512 + h * 64 + 32 + lane] * ipb[512 + h * 64 + 32 + lane];
#pragma unroll
        for (int o = 16; o > 0; o >>= 1) s += __shfl_down_sync(0xffffffffu, s, o);
        if (lane == 0) qb_s[h] = s;
    }
    __syncthreads();
    for (int ti = 0; ti < 2; ti++) {
        int t = q * 8 + w * 2 + ti;
        if (t < Tt) {
            const float* dp = data + (b * Tt + t) * 512;
            for (int hp = 0; hp < 2; hp++) {
                float part[4] = {};
#pragma unroll
                for (int j = 0; j < 4; j++) {
                    float4 d4 = *(const float4*)&dp[j * 128 + lane * 4];
#pragma unroll
                    for (int h4 = 0; h4 < 4; h4++) {
                        float4 r4 = *(const float4*)&rks[(hp * 4 + h4) * 512 + j * 128 + lane * 4];
                        part[h4] += d4.x * r4.x + d4.y * r4.y + d4.z * r4.z + d4.w * r4.w;
                    }
                }
#pragma unroll
                for (int h4 = 0; h4 < 4; h4++) {
                    float s = part[h4];
#pragma unroll
                    for (int o = 16; o > 0; o >>= 1) s += __shfl_down_sync(0xffffffffu, s, o);
                    if (lane == 0) g_scr[(b * Hh + hp * 4 + h4) * 64 + t] = s + qb_s[hp * 4 + h4];
                }
            }
        }
    }
}

// ---------------- softmax + pooled data: grid (4, B), 128 threads ----------------
__global__ void softmax_pool_kernel(const float* __restrict__ data) {
    int b = blockIdx.y, qc = blockIdx.x;
    int tid = threadIdx.x;
    __shared__ float p_s[8][64];
    int w = tid >> 5, lane = tid & 31;
#pragma unroll
    for (int hh = 0; hh < 2; hh++) {
        int h = w * 2 + hh;
        float v0 = (lane < Tt) ? g_scr[(b * Hh + h) * 64 + lane] : -1e30f;
        float v1 = (lane + 32 < Tt) ? g_scr[(b * Hh + h) * 64 + lane + 32] : -1e30f;
        float m = fmaxf(v0, v1);
#pragma unroll
        for (int o = 16; o > 0; o >>= 1) m = fmaxf(m, __shfl_xor_sync(0xffffffffu, m, o));
        float e0 = (lane < Tt) ? expf(v0 - m) : 0.0f;
        float e1 = (lane + 32 < Tt) ? expf(v1 - m) : 0.0f;
        float s = e0 + e1;
#pragma unroll
        for (int o = 16; o > 0; o >>= 1) s += __shfl_xor_sync(0xffffffffu, s, o);
        float inv = 1.0f / s;
        p_s[h][lane] = e0 * inv;
        p_s[h][lane + 32] = e1 * inv;
    }
    __syncthreads();
    int c = qc * 128 + tid;
    float acc[8] = {};
    const float* dpb = data + b * Tt * 512 + c;
#pragma unroll 4
    for (int t = 0; t < Tt; t++) {
        float d = dpb[t * 512];
#pragma unroll
        for (int h = 0; h < 8; h++) acc[h] += p_s[h][t] * d;
    }
#pragma unroll
    for (int h = 0; h < 8; h++)
        g_pd[(b * Hh + h) * 512 + c] = acc[h];
}

// ---------------- router + top-k + beta weights + inlined group build ----------------
__global__ void router_kernel(const float* __restrict__ router_w,
                              const float* __restrict__ router_b,
                              const float* __restrict__ beta_w,
                              const float* __restrict__ beta_b) {
    int b = blockIdx.x;
    __shared__ float tmp_s[512];
    __shared__ float logit[32];
    __shared__ float al[Ee], be[Ee];
    __shared__ int sel_i[Kk];
    __shared__ float w_s[Kk * Tt];
    int tid = threadIdx.x;
    for (int c = tid; c < 512; c += 256) tmp_s[c] = g_tmp[b * Cc + c];
    __syncthreads();
    int w = tid >> 5, lane = tid & 31;
    for (int r = w; r < 30; r += 8) {
        const float* wr; float bias;
        if (r < Ee) { wr = router_w + r * 512; bias = router_b[r]; }
        else { wr = beta_w + (r - Ee) * 512; bias = beta_b[r - Ee]; }
        float s = 0.f;
        for (int c = lane; c < 512; c += 32) s += wr[c] * tmp_s[c];
#pragma unroll
        for (int o = 16; o > 0; o >>= 1) s += __shfl_down_sync(0xffffffffu, s, o);
        if (lane == 0) logit[r] = s + bias;
    }
    __syncthreads();
    if (tid < Ee) {
        al[tid] = softplus_f(logit[Ee + 2 * tid]) + 1e-6f;
        be[tid] = softplus_f(logit[Ee + 2 * tid + 1]) + 1e-6f;
    }
    if (tid == 0) {
        float m = logit[0];
        for (int e = 1; e < Ee; e++) m = fmaxf(m, logit[e]);
        float pe[Ee]; float s = 0.f;
        for (int e = 0; e < Ee; e++) { pe[e] = expf(logit[e] - m); s += pe[e]; }
        float invs = 1.0f / s;
        for (int e = 0; e < Ee; e++) pe[e] *= invs;
        bool used[Ee] = {};
        float psum = 0.f; float sp[Kk];
        for (int kk = 0; kk < Kk; kk++) {
            int best = 0; float bv = -1.f;
            for (int e = 0; e < Ee; e++)
                if (!used[e] && pe[e] > bv) { bv = pe[e]; best = e; }
            used[best] = true; sel_i[kk] = best; sp[kk] = bv; psum += bv;
        }
        float inv = 1.0f / (psum + 1e-8f);
        for (int kk = 0; kk < Kk; kk++) {
            int e = sel_i[kk];
            g_topk_i[b * Kk + kk] = e;
            g_topk_p[b * Kk + kk] = sp[kk] * inv;
            int slot = atomicAdd(&g_cnt[e], 1);
            g_glist[e * 256 + slot] = b * Kk + kk;
        }
    }
    __syncthreads();
    for (int i = tid; i < Kk * Tt; i += 256) {
        int kk = i / Tt, t = i % Tt;
        int e = sel_i[kk];
        float a = al[e], bb = be[e];
        float tt = (float)t / 59.0f;
        float lt = logf(tt + 1e-12f);
        float l1 = logf(1.0f - tt + 1e-12f);
        float norm = lgammaf(a) + lgammaf(bb) - lgammaf(a + bb);
        w_s[i] = expf((a - 1.0f) * lt + (bb - 1.0f) * l1 - norm);
    }
    __syncthreads();
    if (tid < Kk) {
        float m = 0.f;
        for (int t = 0; t < Tt; t++) m = fmaxf(m, w_s[tid * Tt + t]);
        float inv = 1.0f / (m + 1e-8f);
        float s = 0.f;
        for (int t = 0; t < Tt; t++) {
            float v = w_s[tid * Tt + t] * inv;
            g_tw[(b * Kk + tid) * Tt + t] = v;
            s += v;
        }
        g_sw[b * Kk + tid] = s;
    }
}

// ---------------- layer1: fp16 tensor cores, M=64 N=128 tiles, cp.async double-buffered ----------------
#define L1_SMEM 57664
__global__ void layer1_mma_kernel(const float* __restrict__ b1) {
    extern __shared__ char sm[];
    __half* As = (__half*)sm;
    __half* Bs = (__half*)(sm + 18432);
    float* tw_s = (float*)(sm + 55296);
    float* red = (float*)(sm + 55552);
    int bk = blockIdx.y;
    int b = bk / Kk;
    int n0blk = blockIdx.x * 128;
    int e = g_topk_i[bk];
    int tid = threadIdx.x;
    int warp = tid >> 5, lane = tid & 31;
    int mw = warp >> 1, nw = warp & 1;

    if (tid < 64) tw_s[tid] = (tid < Tt) ? g_tw[bk * Tt + tid] : 0.0f;

    const __half* Ap = g_dh + (long)b * (Tt * Cc);
    const __half* Wp = g_w1h + (long)e * (256 * Cc) + (long)n0blk * Cc;

    auto issue = [&](int ch, int buf) {
        int kb = ch * 64;
#pragma unroll
        for (int it = 0; it < 2; it++) {
            int idx = it * 256 + tid;
            int row = idx >> 3, ub = (idx & 7) * 8;
            const __half* a = (row < Tt) ? (Ap + row * Cc + kb + ub) : Ap;
            cp16(smem_u32(As + buf * 4608 + row * 72 + ub), a, row < Tt ? 16 : 0);
        }
#pragma unroll
        for (int it = 0; it < 4; it++) {
            int idx = it * 256 + tid;
            int row = idx >> 3, ub = (idx & 7) * 8;
            cp16(smem_u32(Bs + buf * 9216 + row * 72 + ub), Wp + row * Cc + kb + ub, 16);
        }
        cp_commit();
    };

    float acc[8][4] = {};
    issue(0, 0);
    for (int ch = 0; ch < 8; ch++) {
        int cur = ch & 1;
        if (ch < 7) { issue(ch + 1, cur ^ 1); cp_wait<1>(); }
        else { cp_wait<0>(); }
        __syncthreads();
#pragma unroll
        for (int ks = 0; ks < 4; ks++) {
            uint32_t a[4];
            int arow = mw * 16 + (lane & 15);
            int acol = ks * 16 + (lane >> 4) * 8;
            ldm_x4(a, smem_u32(As + cur * 4608 + arow * 72 + acol));
            uint32_t bf[16];
#pragma unroll
            for (int half = 0; half < 4; half++) {
                int nbase = nw * 64 + half * 16;
                int grp = lane >> 3, l8 = lane & 7;
                int nrow = nbase + (grp >> 1) * 8 + l8;
                int kcol = ks * 16 + (grp & 1) * 8;
                ldm_x4(bf + half * 4, smem_u32(Bs + cur * 9216 + nrow * 72 + kcol));
            }
#pragma unroll
            for (int j = 0; j < 8; j++) mma16816(acc[j], a, bf + j * 2);
        }
        __syncthreads();
    }
    int g = lane >> 2, t4 = lane & 3;
    int r0 = mw * 16 + g, r1 = r0 + 8;
    float w0 = tw_s[r0], w1 = tw_s[r1];
#pragma unroll
    for (int j = 0; j < 8; j++) {
        int nc0 = nw * 64 + j * 8 + t4 * 2;
        float bias0 = b1[e * 256 + n0blk + nc0];
        float bias1 = b1[e * 256 + n0blk + nc0 + 1];
        float s0 = w0 * fmaxf(acc[j][0] + bias0, 0.f) + w1 * fmaxf(acc[j][2] + bias0, 0.f);
        float s1 = w0 * fmaxf(acc[j][1] + bias1, 0.f) + w1 * fmaxf(acc[j][3] + bias1, 0.f);
#pragma unroll
        for (int o = 16; o >= 4; o >>= 1) {
            s0 += __shfl_down_sync(0xffffffffu, s0, o);
            s1 += __shfl_down_sync(0xffffffffu, s1, o);
        }
        if (g == 0) {
            red[mw * 132 + nc0] = s0;
            red[mw * 132 + nc0 + 1] = s1;
        }
    }
    __syncthreads();
    if (tid < 128) {
        float p = red[tid] + red[132 + tid] + red[264 + tid] + red[396 + tid];
        g_pooled[bk * 256 + n0blk + tid] = p;
    }
}

// ---------------- layer2: expert-grouped GEMM ----------------
__global__ void layer2_kernel(const float* __restrict__ w2,
                              const float* __restrict__ b2) {
    int nt = blockIdx.x, mt = blockIdx.y, e = blockIdx.z;
    int cnt = g_cnt[e];
    if (mt * 32 >= cnt) return;
    __shared__ float P[32 * 260];
    __shared__ float Ws[64 * 65];
    __shared__ int prs[32];
    int tid = threadIdx.x;
    int rows = cnt - mt * 32; if (rows > 32) rows = 32;
    if (tid < 32) prs[tid] = (tid < rows) ? g_glist[e * 256 + mt * 32 + tid] : -1;
    __syncthreads();
#pragma unroll
    for (int r = 0; r < 8; r++) {
        int fi = r * 256 + tid;
        int row = fi >> 6, c4 = (fi & 63) * 4;
        float4 v = make_float4(0.f, 0.f, 0.f, 0.f);
        int p = prs[row];
        if (p >= 0) v = *(const float4*)&g_pooled[p * 256 + c4];
        *(float4*)&P[row * 260 + c4] = v;
    }
    int nn = tid & 31, mg = tid >> 5;
    float acc[4][2] = {};
    for (int q = 0; q < 4; q++) {
        __syncthreads();
#pragma unroll
        for (int r = 0; r < 16; r++) {
            int fi = r * 256 + tid;
            int n = fi >> 6, kc = fi & 63;
            Ws[n * 65 + kc] = w2[(e * 512 + nt * 64 + n) * 256 + q * 64 + kc];
        }
        __syncthreads();
#pragma unroll 4
        for (int kc = 0; kc < 64; kc++) {
            float w0 = Ws[nn * 65 + kc];
            float w1 = Ws[(nn + 32) * 65 + kc];
#pragma unroll
            for (int mi = 0; mi < 4; mi++) {
                float pv = P[(mg + mi * 8) * 260 + q * 64 + kc];
                acc[mi][0] += pv * w0;
                acc[mi][1] += pv * w1;
            }
        }
    }
#pragma unroll
    for (int mi = 0; mi < 4; mi++) {
        int row = mg + mi * 8;
        int p = prs[row];
        if (p >= 0) {
            float sw = g_sw[p];
            int cc0 = nt * 64 + nn, cc1 = cc0 + 32;
            g_perexp[p * 512 + cc0] = acc[mi][0] + sw * b2[e * 512 + cc0];
            g_perexp[p * 512 + cc1] = acc[mi][1] + sw * b2[e * 512 + cc1];
        }
    }
}

// ---------------- combine + LayerNorm ----------------
__global__ void ln_kernel(const float* __restrict__ ln_g,
                          const float* __restrict__ ln_b,
                          float* __restrict__ out) {
    int b = blockIdx.x, tid = threadIdx.x;
    __shared__ float red[18];
    float y0 = 0.f, y1 = 0.f;
#pragma unroll
    for (int kk = 0; kk < Kk; kk++) {
        float p = g_topk_p[b * Kk + kk];
        const float* pe = g_perexp + (b * Kk + kk) * 512;
        y0 += p * pe[tid];
        y1 += p * pe[tid + 256];
    }
    float s = y0 + y1, sq = y0 * y0 + y1 * y1;
    int w = tid >> 5, lane = tid & 31;
#pragma unroll
    for (int o = 16; o > 0; o >>= 1) {
        s += __shfl_down_sync(0xffffffffu, s, o);
        sq += __shfl_down_sync(0xffffffffu, sq, o);
    }
    if (lane == 0) { red[w] = s; red[8 + w] = sq; }
    __syncthreads();
    if (tid == 0) {
        float S = 0.f, SQ = 0.f;
        for (int i = 0; i < 8; i++) { S += red[i]; SQ += red[8 + i]; }
        red[16] = S; red[17] = SQ;
    }
    __syncthreads();
    float mean = red[16] * (1.0f / 512.0f);
    float var = red[17] * (1.0f / 512.0f) - mean * mean;
    float rstd = rsqrtf(var + 1e-5f);
    out[b * Cc + tid] = (y0 - mean) * rstd * ln_g[tid] + ln_b[tid];
    out[b * Cc + tid + 256] = (y1 - mean) * rstd * ln_g[tid + 256] + ln_b[tid + 256];
}

// ---------------- launch ----------------
extern "C" void kernel_launch(void* const* d_in, const int* in_sizes, int n_in,
                              void* d_out, int out_size) {
    const float* qst = (const float*)d_in[0];
    const float* data = (const float*)d_in[1];
    const float* ipw = (const float*)d_in[2];
    const float* ipb = (const float*)d_in[3];
    const float* opw = (const float*)d_in[4];
    const float* opb = (const float*)d_in[5];
    const float* rw  = (const float*)d_in[6];
    const float* rb  = (const float*)d_in[7];
    const float* bw  = (const float*)d_in[8];
    const float* bb  = (const float*)d_in[9];
    const float* w1  = (const float*)d_in[10];
    const float* b1  = (const float*)d_in[11];
    const float* w2  = (const float*)d_in[12];
    const float* b2  = (const float*)d_in[13];
    const float* lng = (const float*)d_in[14];
    const float* lnb = (const float*)d_in[15];
    float* out = (float*)d_out;

    static bool attr_done = false;
    if (!attr_done) {
        cudaFuncSetAttribute(layer1_mma_kernel,
                             cudaFuncAttributeMaxDynamicSharedMemorySize, L1_SMEM);
        attr_done = true;
    }

    prep_kernel<<<(Bb * Tt * Cc / 4 + 255) / 256, 256>>>(data, w1);
    proj_q_kernel<<<dim3(8, 8), 256>>>(qst, ipw, ipb);
    rk_kernel<<<dim3(8, 8, 8), 256>>>(ipw);
    score_kernel<<<dim3(8, Bb), 128>>>(data, ipb);
    softmax_pool_kernel<<<dim3(4, Bb), 128>>>(data);
    ctx_kernel<<<dim3(8, 8), 256>>>(ipw, ipb);
    proj_tmp_kernel<<<dim3(8, 8), 256>>>(opw, opb);
    router_kernel<<<Bb, 256>>>(rw, rb, bw, bb);
    layer1_mma_kernel<<<dim3(2, Bb * Kk), 256, L1_SMEM>>>(b1);
    layer2_kernel<<<dim3(8, 8, Ee), 256>>>(w2, b2);
    ln_kernel<<<Bb, 256>>>(lng, lnb, out);
}

// round 16
// speedup vs baseline: 1.2560x; 1.0518x over previous
#include <cuda_runtime.h>
#include <cuda_fp16.h>
#include <cstdint>
#include <math.h>

#define Bb 256
#define Tt 60
#define Cc 512
#define Ee 10
#define Kk 5
#define Hh 8
#define DH 64

// ---------------- scratch (device globals) ----------------
__device__ float g_q[Bb * Cc];
__device__ float g_rk[Bb * Hh * Cc];
__device__ float g_ctx[Bb * Cc];
__device__ float g_tmp[Bb * Cc];
__device__ float g_scr[Bb * Hh * 64];
__device__ int   g_topk_i[Bb * Kk];
__device__ float g_topk_p[Bb * Kk];
__device__ float g_tw[Bb * Kk * Tt];
__device__ float g_sw[Bb * Kk];
__device__ float g_pooled[Bb * Kk * 256];
__device__ float g_pd[Bb * Hh * Cc];
__device__ float g_perexp[Bb * Kk * Cc];
__device__ int   g_glist[Ee * 256];
__device__ int   g_cnt[Ee];
__device__ __half g_dh[Bb * Tt * Cc];
__device__ __half g_w1h[Ee * 256 * Cc];

// ---------------- helpers ----------------
__device__ __forceinline__ float softplus_f(float x) {
    return fmaxf(x, 0.0f) + log1pf(expf(-fabsf(x)));
}
__device__ __forceinline__ uint32_t smem_u32(const void* p) {
    return (uint32_t)__cvta_generic_to_shared(p);
}
__device__ __forceinline__ void ldm_x4(uint32_t* r, uint32_t addr) {
    asm volatile("ldmatrix.sync.aligned.m8n8.x4.shared.b16 {%0,%1,%2,%3}, [%4];"
                 : "=r"(r[0]), "=r"(r[1]), "=r"(r[2]), "=r"(r[3]) : "r"(addr));
}
__device__ __forceinline__ void mma16816(float* c, const uint32_t* a, const uint32_t* b) {
    asm volatile(
        "mma.sync.aligned.m16n8k16.row.col.f32.f16.f16.f32 "
        "{%0,%1,%2,%3}, {%4,%5,%6,%7}, {%8,%9}, {%0,%1,%2,%3};"
        : "+f"(c[0]), "+f"(c[1]), "+f"(c[2]), "+f"(c[3])
        : "r"(a[0]), "r"(a[1]), "r"(a[2]), "r"(a[3]), "r"(b[0]), "r"(b[1]));
}
__device__ __forceinline__ void cp16(uint32_t dst, const void* src, int srcsize) {
    asm volatile("cp.async.cg.shared.global [%0], [%1], 16, %2;\n"
                 :: "r"(dst), "l"(src), "r"(srcsize));
}
__device__ __forceinline__ void cp_commit() {
    asm volatile("cp.async.commit_group;\n");
}
template <int N>
__device__ __forceinline__ void cp_wait() {
    asm volatile("cp.async.wait_group %0;\n" :: "n"(N));
}

// ---------------- prep: fp16 conversions (x4 vectorized) + g_cnt zeroing ----------------
__global__ void prep_kernel(const float* __restrict__ data, const float* __restrict__ w1) {
    int i = (blockIdx.x * 256 + threadIdx.x) * 4;
    if (i < Bb * Tt * Cc) {
        float4 v = *(const float4*)(data + i);
        *(__half2*)(g_dh + i) = __floats2half2_rn(v.x, v.y);
        *(__half2*)(g_dh + i + 2) = __floats2half2_rn(v.z, v.w);
    }
    if (i < Ee * 256 * Cc) {
        float4 v = *(const float4*)(w1 + i);
        *(__half2*)(g_w1h + i) = __floats2half2_rn(v.x, v.y);
        *(__half2*)(g_w1h + i + 2) = __floats2half2_rn(v.z, v.w);
    }
    int t = blockIdx.x * 256 + threadIdx.x;
    if (t < Ee) g_cnt[t] = 0;
}

// ---------------- generic 32x64 SGEMM, double-buffered, k-step 32 ----------------
__device__ __forceinline__ void sgemm_body32(const float* __restrict__ A, int lda,
                                             const float* __restrict__ W,
                                             const float* __restrict__ bias,
                                             float* __restrict__ C, int ldc,
                                             float alpha, int n0, int m0) {
    __shared__ float As[2][32 * 36];
    __shared__ float Ws[2][32 * 68];
    int tid = threadIdx.x;
    int ty = tid >> 4, tx = tid & 15;
    float acc[2][4] = {};
    float ar[4], wr[8];
#pragma unroll
    for (int r = 0; r < 4; r++) { int l = r * 256 + tid; int m = l >> 5, kc = l & 31; ar[r] = A[(m0 + m) * lda + kc]; }
#pragma unroll
    for (int r = 0; r < 8; r++) { int l = r * 256 + tid; int n = l >> 5, kc = l & 31; wr[r] = W[(n0 + n) * 512 + kc]; }
#pragma unroll
    for (int r = 0; r < 4; r++) { int l = r * 256 + tid; int m = l >> 5, kc = l & 31; As[0][kc * 36 + m] = ar[r]; }
#pragma unroll
    for (int r = 0; r < 8; r++) { int l = r * 256 + tid; int n = l >> 5, kc = l & 31; Ws[0][kc * 68 + n] = wr[r]; }
    for (int i = 0; i < 16; i++) {
        int cur = i & 1;
        if (i < 15) {
            int k0 = (i + 1) * 32;
#pragma unroll
            for (int r = 0; r < 4; r++) { int l = r * 256 + tid; int m = l >> 5, kc = l & 31; ar[r] = A[(m0 + m) * lda + k0 + kc]; }
#pragma unroll
            for (int r = 0; r < 8; r++) { int l = r * 256 + tid; int n = l >> 5, kc = l & 31; wr[r] = W[(n0 + n) * 512 + k0 + kc]; }
        }
        __syncthreads();
#pragma unroll
        for (int kc = 0; kc < 32; kc++) {
            float a0 = As[cur][kc * 36 + ty * 2];
            float a1 = As[cur][kc * 36 + ty * 2 + 1];
            float4 bv = *(const float4*)&Ws[cur][kc * 68 + tx * 4];
            acc[0][0] += a0 * bv.x; acc[0][1] += a0 * bv.y;
            acc[0][2] += a0 * bv.z; acc[0][3] += a0 * bv.w;
            acc[1][0] += a1 * bv.x; acc[1][1] += a1 * bv.y;
            acc[1][2] += a1 * bv.z; acc[1][3] += a1 * bv.w;
        }
        if (i < 15) {
            int nb = cur ^ 1;
#pragma unroll
            for (int r = 0; r < 4; r++) { int l = r * 256 + tid; int m = l >> 5, kc = l & 31; As[nb][kc * 36 + m] = ar[r]; }
#pragma unroll
            for (int r = 0; r < 8; r++) { int l = r * 256 + tid; int n = l >> 5, kc = l & 31; Ws[nb][kc * 68 + n] = wr[r]; }
        }
    }
#pragma unroll
    for (int i = 0; i < 2; i++) {
        int m = m0 + ty * 2 + i;
#pragma unroll
        for (int j = 0; j < 4; j++) {
            int n = n0 + tx * 4 + j;
            C[m * ldc + n] = alpha * (acc[i][j] + bias[n]);
        }
    }
}
__global__ void proj_q_kernel(const float* __restrict__ qst,
                              const float* __restrict__ ipw,
                              const float* __restrict__ ipb) {
    sgemm_body32(qst, 512, ipw, ipb, g_q, 512, 0.125f, blockIdx.x * 64, blockIdx.y * 32);
}
__global__ void proj_tmp_kernel(const float* __restrict__ opw,
                                const float* __restrict__ opb) {
    sgemm_body32(g_ctx, 512, opw, opb, g_tmp, 512, 1.0f, blockIdx.x * 64, blockIdx.y * 32);
}
__global__ void ctx_kernel(const float* __restrict__ ipw,
                           const float* __restrict__ ipb) {
    int h = blockIdx.x;
    sgemm_body32(g_pd + h * 512, Hh * 512,
                 ipw + (1024 + h * 64) * 512,
                 ipb + 1024 + h * 64,
                 g_ctx + h * 64, 512, 1.0f, 0, blockIdx.y * 32);
}

// ---------------- rk = q_h @ Wk_h : 32x64 tiles, grid (8n, 8m, 8h) ----------------
__global__ void rk_kernel(const float* __restrict__ ipw) {
    __shared__ float As[16 * 36];
    __shared__ float Ws[16 * 68];
    int n0 = blockIdx.x * 64, m0 = blockIdx.y * 32, h = blockIdx.z;
    int tid = threadIdx.x, ty = tid >> 4, tx = tid & 15;
    float acc[2][4] = {};
    for (int kk = 0; kk < 64; kk += 16) {
#pragma unroll
        for (int r = 0; r < 2; r++) {
            int l = r * 256 + tid;
            int m = l >> 4, kc = l & 15;
            As[kc * 36 + m] = g_q[(m0 + m) * 512 + h * 64 + kk + kc];
        }
#pragma unroll
        for (int r = 0; r < 4; r++) {
            int l = r * 256 + tid;
            int kc = l >> 6, n = l & 63;
            Ws[kc * 68 + n] = ipw[(512 + h * 64 + kk + kc) * 512 + n0 + n];
        }
        __syncthreads();
#pragma unroll
        for (int kc = 0; kc < 16; kc++) {
            float a0 = As[kc * 36 + ty * 2];
            float a1 = As[kc * 36 + ty * 2 + 1];
            float4 bv = *(const float4*)&Ws[kc * 68 + tx * 4];
            acc[0][0] += a0 * bv.x; acc[0][1] += a0 * bv.y;
            acc[0][2] += a0 * bv.z; acc[0][3] += a0 * bv.w;
            acc[1][0] += a1 * bv.x; acc[1][1] += a1 * bv.y;
            acc[1][2] += a1 * bv.z; acc[1][3] += a1 * bv.w;
        }
        __syncthreads();
    }
#pragma unroll
    for (int i = 0; i < 2; i++) {
        int b = m0 + ty * 2 + i;
#pragma unroll
        for (int j = 0; j < 4; j++)
            g_rk[(b * Hh + h) * 512 + n0 + tx * 4 + j] = acc[i][j];
    }
}

// ---------------- attention scores: grid (4, B), 128 threads, 15 t per block ----------------
__global__ void score_kernel(const float* __restrict__ data,
                             const float* __restrict__ ipb) {
    int b = blockIdx.y, q = blockIdx.x;
    int tid = threadIdx.x;
    __shared__ float rks[8 * 512];
    __shared__ float qb_s[8];
    const float* rkg = g_rk + b * (Hh * 512);
    for (int i = tid * 4; i < 4096; i += 512)
        *(float4*)&rks[i] = *(const float4*)&rkg[i];
    int w = tid >> 5, lane = tid & 31;
#pragma unroll
    for (int hh = 0; hh < 2; hh++) {
        int h = w * 2 + hh;
        float s = g_q[b * 512 + h * 64 + lane] * ipb[512 + h * 64 + lane]
                + g_q[b * 512 + h * 64 + 32 + lane] * ipb[512 + h * 64 + 32 + lane];
#pragma unroll
        for (int o = 16; o > 0; o >>= 1) s += __shfl_down_sync(0xffffffffu, s, o);
        if (lane == 0) qb_s[h] = s;
    }
    __syncthreads();
    for (int ti = 0; ti < 4; ti++) {
        int tl = w * 4 + ti;
        if (tl < 15) {
            int t = q * 15 + tl;
            const float* dp = data + (b * Tt + t) * 512;
            for (int hp = 0; hp < 2; hp++) {
                float part[4] = {};
#pragma unroll
                for (int j = 0; j < 4; j++) {
                    float4 d4 = *(const float4*)&dp[j * 128 + lane * 4];
#pragma unroll
                    for (int h4 = 0; h4 < 4; h4++) {
                        float4 r4 = *(const float4*)&rks[(hp * 4 + h4) * 512 + j * 128 + lane * 4];
                        part[h4] += d4.x * r4.x + d4.y * r4.y + d4.z * r4.z + d4.w * r4.w;
                    }
                }
#pragma unroll
                for (int h4 = 0; h4 < 4; h4++) {
                    float s = part[h4];
#pragma unroll
                    for (int o = 16; o > 0; o >>= 1) s += __shfl_down_sync(0xffffffffu, s, o);
                    if (lane == 0) g_scr[(b * Hh + hp * 4 + h4) * 64 + t] = s + qb_s[hp * 4 + h4];
                }
            }
        }
    }
}

// ---------------- softmax + pooled data: grid (4, B), 128 threads ----------------
__global__ void softmax_pool_kernel(const float* __restrict__ data) {
    int b = blockIdx.y, qc = blockIdx.x;
    int tid = threadIdx.x;
    __shared__ float p_s[8][64];
    int w = tid >> 5, lane = tid & 31;
#pragma unroll
    for (int hh = 0; hh < 2; hh++) {
        int h = w * 2 + hh;
        float v0 = (lane < Tt) ? g_scr[(b * Hh + h) * 64 + lane] : -1e30f;
        float v1 = (lane + 32 < Tt) ? g_scr[(b * Hh + h) * 64 + lane + 32] : -1e30f;
        float m = fmaxf(v0, v1);
#pragma unroll
        for (int o = 16; o > 0; o >>= 1) m = fmaxf(m, __shfl_xor_sync(0xffffffffu, m, o));
        float e0 = (lane < Tt) ? expf(v0 - m) : 0.0f;
        float e1 = (lane + 32 < Tt) ? expf(v1 - m) : 0.0f;
        float s = e0 + e1;
#pragma unroll
        for (int o = 16; o > 0; o >>= 1) s += __shfl_xor_sync(0xffffffffu, s, o);
        float inv = 1.0f / s;
        p_s[h][lane] = e0 * inv;
        p_s[h][lane + 32] = e1 * inv;
    }
    __syncthreads();
    int c = qc * 128 + tid;
    float acc[8] = {};
    const float* dpb = data + b * Tt * 512 + c;
#pragma unroll 4
    for (int t = 0; t < Tt; t++) {
        float d = dpb[t * 512];
#pragma unroll
        for (int h = 0; h < 8; h++) acc[h] += p_s[h][t] * d;
    }
#pragma unroll
    for (int h = 0; h < 8; h++)
        g_pd[(b * Hh + h) * 512 + c] = acc[h];
}

// ---------------- router + top-k + beta weights + inlined group build ----------------
__global__ void router_kernel(const float* __restrict__ router_w,
                              const float* __restrict__ router_b,
                              const float* __restrict__ beta_w,
                              const float* __restrict__ beta_b) {
    int b = blockIdx.x;
    __shared__ float tmp_s[512];
    __shared__ float logit[32];
    __shared__ float al[Ee], be[Ee];
    __shared__ int sel_i[Kk];
    __shared__ float w_s[Kk * Tt];
    int tid = threadIdx.x;
    for (int c = tid; c < 512; c += 256) tmp_s[c] = g_tmp[b * Cc + c];
    __syncthreads();
    int w = tid >> 5, lane = tid & 31;
    for (int r = w; r < 30; r += 8) {
        const float* wr; float bias;
        if (r < Ee) { wr = router_w + r * 512; bias = router_b[r]; }
        else { wr = beta_w + (r - Ee) * 512; bias = beta_b[r - Ee]; }
        float s = 0.f;
        for (int c = lane; c < 512; c += 32) s += wr[c] * tmp_s[c];
#pragma unroll
        for (int o = 16; o > 0; o >>= 1) s += __shfl_down_sync(0xffffffffu, s, o);
        if (lane == 0) logit[r] = s + bias;
    }
    __syncthreads();
    if (tid < Ee) {
        al[tid] = softplus_f(logit[Ee + 2 * tid]) + 1e-6f;
        be[tid] = softplus_f(logit[Ee + 2 * tid + 1]) + 1e-6f;
    }
    if (tid == 0) {
        float m = logit[0];
        for (int e = 1; e < Ee; e++) m = fmaxf(m, logit[e]);
        float pe[Ee]; float s = 0.f;
        for (int e = 0; e < Ee; e++) { pe[e] = expf(logit[e] - m); s += pe[e]; }
        float invs = 1.0f / s;
        for (int e = 0; e < Ee; e++) pe[e] *= invs;
        bool used[Ee] = {};
        float psum = 0.f; float sp[Kk];
        for (int kk = 0; kk < Kk; kk++) {
            int best = 0; float bv = -1.f;
            for (int e = 0; e < Ee; e++)
                if (!used[e] && pe[e] > bv) { bv = pe[e]; best = e; }
            used[best] = true; sel_i[kk] = best; sp[kk] = bv; psum += bv;
        }
        float inv = 1.0f / (psum + 1e-8f);
        for (int kk = 0; kk < Kk; kk++) {
            int e = sel_i[kk];
            g_topk_i[b * Kk + kk] = e;
            g_topk_p[b * Kk + kk] = sp[kk] * inv;
            int slot = atomicAdd(&g_cnt[e], 1);
            g_glist[e * 256 + slot] = b * Kk + kk;
        }
    }
    __syncthreads();
    for (int i = tid; i < Kk * Tt; i += 256) {
        int kk = i / Tt, t = i % Tt;
        int e = sel_i[kk];
        float a = al[e], bb = be[e];
        float tt = (float)t / 59.0f;
        float lt = logf(tt + 1e-12f);
        float l1 = logf(1.0f - tt + 1e-12f);
        float norm = lgammaf(a) + lgammaf(bb) - lgammaf(a + bb);
        w_s[i] = expf((a - 1.0f) * lt + (bb - 1.0f) * l1 - norm);
    }
    __syncthreads();
    if (tid < Kk) {
        float m = 0.f;
        for (int t = 0; t < Tt; t++) m = fmaxf(m, w_s[tid * Tt + t]);
        float inv = 1.0f / (m + 1e-8f);
        float s = 0.f;
        for (int t = 0; t < Tt; t++) {
            float v = w_s[tid * Tt + t] * inv;
            g_tw[(b * Kk + tid) * Tt + t] = v;
            s += v;
        }
        g_sw[b * Kk + tid] = s;
    }
}

// ---------------- layer1: fp16 tensor cores, M=64 N=128 tiles, cp.async double-buffered ----------------
#define L1_SMEM 57664
__global__ void layer1_mma_kernel(const float* __restrict__ b1) {
    extern __shared__ char sm[];
    __half* As = (__half*)sm;
    __half* Bs = (__half*)(sm + 18432);
    float* tw_s = (float*)(sm + 55296);
    float* red = (float*)(sm + 55552);
    int bk = blockIdx.y;
    int b = bk / Kk;
    int n0blk = blockIdx.x * 128;
    int e = g_topk_i[bk];
    int tid = threadIdx.x;
    int warp = tid >> 5, lane = tid & 31;
    int mw = warp >> 1, nw = warp & 1;

    if (tid < 64) tw_s[tid] = (tid < Tt) ? g_tw[bk * Tt + tid] : 0.0f;

    const __half* Ap = g_dh + (long)b * (Tt * Cc);
    const __half* Wp = g_w1h + (long)e * (256 * Cc) + (long)n0blk * Cc;

    auto issue = [&](int ch, int buf) {
        int kb = ch * 64;
#pragma unroll
        for (int it = 0; it < 2; it++) {
            int idx = it * 256 + tid;
            int row = idx >> 3, ub = (idx & 7) * 8;
            const __half* a = (row < Tt) ? (Ap + row * Cc + kb + ub) : Ap;
            cp16(smem_u32(As + buf * 4608 + row * 72 + ub), a, row < Tt ? 16 : 0);
        }
#pragma unroll
        for (int it = 0; it < 4; it++) {
            int idx = it * 256 + tid;
            int row = idx >> 3, ub = (idx & 7) * 8;
            cp16(smem_u32(Bs + buf * 9216 + row * 72 + ub), Wp + row * Cc + kb + ub, 16);
        }
        cp_commit();
    };

    float acc[8][4] = {};
    issue(0, 0);
    for (int ch = 0; ch < 8; ch++) {
        int cur = ch & 1;
        if (ch < 7) { issue(ch + 1, cur ^ 1); cp_wait<1>(); }
        else { cp_wait<0>(); }
        __syncthreads();
#pragma unroll
        for (int ks = 0; ks < 4; ks++) {
            uint32_t a[4];
            int arow = mw * 16 + (lane & 15);
            int acol = ks * 16 + (lane >> 4) * 8;
            ldm_x4(a, smem_u32(As + cur * 4608 + arow * 72 + acol));
            uint32_t bf[16];
#pragma unroll
            for (int half = 0; half < 4; half++) {
                int nbase = nw * 64 + half * 16;
                int grp = lane >> 3, l8 = lane & 7;
                int nrow = nbase + (grp >> 1) * 8 + l8;
                int kcol = ks * 16 + (grp & 1) * 8;
                ldm_x4(bf + half * 4, smem_u32(Bs + cur * 9216 + nrow * 72 + kcol));
            }
#pragma unroll
            for (int j = 0; j < 8; j++) mma16816(acc[j], a, bf + j * 2);
        }
        __syncthreads();
    }
    int g = lane >> 2, t4 = lane & 3;
    int r0 = mw * 16 + g, r1 = r0 + 8;
    float w0 = tw_s[r0], w1 = tw_s[r1];
#pragma unroll
    for (int j = 0; j < 8; j++) {
        int nc0 = nw * 64 + j * 8 + t4 * 2;
        float bias0 = b1[e * 256 + n0blk + nc0];
        float bias1 = b1[e * 256 + n0blk + nc0 + 1];
        float s0 = w0 * fmaxf(acc[j][0] + bias0, 0.f) + w1 * fmaxf(acc[j][2] + bias0, 0.f);
        float s1 = w0 * fmaxf(acc[j][1] + bias1, 0.f) + w1 * fmaxf(acc[j][3] + bias1, 0.f);
#pragma unroll
        for (int o = 16; o >= 4; o >>= 1) {
            s0 += __shfl_down_sync(0xffffffffu, s0, o);
            s1 += __shfl_down_sync(0xffffffffu, s1, o);
        }
        if (g == 0) {
            red[mw * 132 + nc0] = s0;
            red[mw * 132 + nc0 + 1] = s1;
        }
    }
    __syncthreads();
    if (tid < 128) {
        float p = red[tid] + red[132 + tid] + red[264 + tid] + red[396 + tid];
        g_pooled[bk * 256 + n0blk + tid] = p;
    }
}

// ---------------- layer2: expert-grouped GEMM, W2 register-prefetched ----------------
__global__ void layer2_kernel(const float* __restrict__ w2,
                              const float* __restrict__ b2) {
    int nt = blockIdx.x, mt = blockIdx.y, e = blockIdx.z;
    int cnt = g_cnt[e];
    if (mt * 32 >= cnt) return;
    __shared__ float P[32 * 260];
    __shared__ float Ws[64 * 65];
    __shared__ int prs[32];
    int tid = threadIdx.x;
    int rows = cnt - mt * 32; if (rows > 32) rows = 32;
    if (tid < 32) prs[tid] = (tid < rows) ? g_glist[e * 256 + mt * 32 + tid] : -1;
    __syncthreads();
    // prefetch W2 chunk q=0 into regs
    float wpre[16];
#pragma unroll
    for (int r = 0; r < 16; r++) {
        int fi = r * 256 + tid;
        int n = fi >> 6, kc = fi & 63;
        wpre[r] = w2[(e * 512 + nt * 64 + n) * 256 + kc];
    }
#pragma unroll
    for (int r = 0; r < 8; r++) {
        int fi = r * 256 + tid;
        int row = fi >> 6, c4 = (fi & 63) * 4;
        float4 v = make_float4(0.f, 0.f, 0.f, 0.f);
        int p = prs[row];
        if (p >= 0) v = *(const float4*)&g_pooled[p * 256 + c4];
        *(float4*)&P[row * 260 + c4] = v;
    }
    int nn = tid & 31, mg = tid >> 5;
    float acc[4][2] = {};
    for (int q = 0; q < 4; q++) {
        __syncthreads();
#pragma unroll
        for (int r = 0; r < 16; r++) {
            int fi = r * 256 + tid;
            int n = fi >> 6, kc = fi & 63;
            Ws[n * 65 + kc] = wpre[r];
        }
        __syncthreads();
        if (q < 3) {
#pragma unroll
            for (int r = 0; r < 16; r++) {
                int fi = r * 256 + tid;
                int n = fi >> 6, kc = fi & 63;
                wpre[r] = w2[(e * 512 + nt * 64 + n) * 256 + (q + 1) * 64 + kc];
            }
        }
#pragma unroll 4
        for (int kc = 0; kc < 64; kc++) {
            float w0 = Ws[nn * 65 + kc];
            float w1 = Ws[(nn + 32) * 65 + kc];
#pragma unroll
            for (int mi = 0; mi < 4; mi++) {
                float pv = P[(mg + mi * 8) * 260 + q * 64 + kc];
                acc[mi][0] += pv * w0;
                acc[mi][1] += pv * w1;
            }
        }
    }
#pragma unroll
    for (int mi = 0; mi < 4; mi++) {
        int row = mg + mi * 8;
        int p = prs[row];
        if (p >= 0) {
            float sw = g_sw[p];
            int cc0 = nt * 64 + nn, cc1 = cc0 + 32;
            g_perexp[p * 512 + cc0] = acc[mi][0] + sw * b2[e * 512 + cc0];
            g_perexp[p * 512 + cc1] = acc[mi][1] + sw * b2[e * 512 + cc1];
        }
    }
}

// ---------------- combine + LayerNorm ----------------
__global__ void ln_kernel(const float* __restrict__ ln_g,
                          const float* __restrict__ ln_b,
                          float* __restrict__ out) {
    int b = blockIdx.x, tid = threadIdx.x;
    __shared__ float red[18];
    float y0 = 0.f, y1 = 0.f;
#pragma unroll
    for (int kk = 0; kk < Kk; kk++) {
        float p = g_topk_p[b * Kk + kk];
        const float* pe = g_perexp + (b * Kk + kk) * 512;
        y0 += p * pe[tid];
        y1 += p * pe[tid + 256];
    }
    float s = y0 + y1, sq = y0 * y0 + y1 * y1;
    int w = tid >> 5, lane = tid & 31;
#pragma unroll
    for (int o = 16; o > 0; o >>= 1) {
        s += __shfl_down_sync(0xffffffffu, s, o);
        sq += __shfl_down_sync(0xffffffffu, sq, o);
    }
    if (lane == 0) { red[w] = s; red[8 + w] = sq; }
    __syncthreads();
    if (tid == 0) {
        float S = 0.f, SQ = 0.f;
        for (int i = 0; i < 8; i++) { S += red[i]; SQ += red[8 + i]; }
        red[16] = S; red[17] = SQ;
    }
    __syncthreads();
    float mean = red[16] * (1.0f / 512.0f);
    float var = red[17] * (1.0f / 512.0f) - mean * mean;
    float rstd = rsqrtf(var + 1e-5f);
    out[b * Cc + tid] = (y0 - mean) * rstd * ln_g[tid] + ln_b[tid];
    out[b * Cc + tid + 256] = (y1 - mean) * rstd * ln_g[tid + 256] + ln_b[tid + 256];
}

// ---------------- launch ----------------
extern "C" void kernel_launch(void* const* d_in, const int* in_sizes, int n_in,
                              void* d_out, int out_size) {
    const float* qst = (const float*)d_in[0];
    const float* data = (const float*)d_in[1];
    const float* ipw = (const float*)d_in[2];
    const float* ipb = (const float*)d_in[3];
    const float* opw = (const float*)d_in[4];
    const float* opb = (const float*)d_in[5];
    const float* rw  = (const float*)d_in[6];
    const float* rb  = (const float*)d_in[7];
    const float* bw  = (const float*)d_in[8];
    const float* bb  = (const float*)d_in[9];
    const float* w1  = (const float*)d_in[10];
    const float* b1  = (const float*)d_in[11];
    const float* w2  = (const float*)d_in[12];
    const float* b2  = (const float*)d_in[13];
    const float* lng = (const float*)d_in[14];
    const float* lnb = (const float*)d_in[15];
    float* out = (float*)d_out;

    static bool attr_done = false;
    if (!attr_done) {
        cudaFuncSetAttribute(layer1_mma_kernel,
                             cudaFuncAttributeMaxDynamicSharedMemorySize, L1_SMEM);
        attr_done = true;
    }

    prep_kernel<<<(Bb * Tt * Cc / 4 + 255) / 256, 256>>>(data, w1);
    proj_q_kernel<<<dim3(8, 8), 256>>>(qst, ipw, ipb);
    rk_kernel<<<dim3(8, 8, 8), 256>>>(ipw);
    score_kernel<<<dim3(4, Bb), 128>>>(data, ipb);
    softmax_pool_kernel<<<dim3(4, Bb), 128>>>(data);
    ctx_kernel<<<dim3(8, 8), 256>>>(ipw, ipb);
    proj_tmp_kernel<<<dim3(8, 8), 256>>>(opw, opb);
    router_kernel<<<Bb, 256>>>(rw, rb, bw, bb);
    layer1_mma_kernel<<<dim3(2, Bb * Kk), 256, L1_SMEM>>>(b1);
    layer2_kernel<<<dim3(8, 8, Ee), 256>>>(w2, b2);
    ln_kernel<<<Bb, 256>>>(lng, lnb, out);
}